// round 16
// baseline (speedup 1.0000x reference)
#include <cuda_runtime.h>
#include <cuda_fp16.h>
#include <cstdint>

#define NN   100000
#define NE   3200000
#define FH   128
#define FIN  100
#define BNEPS 1e-5f
#define CAP  128       // bucket slots/node == agg row size; Poisson(32) tail ~e^-90
#define KSTEPS 13      // K=100 padded to 104 = 13 x 8

// ---------------- scratch (static device globals; no allocation) ----------------
// g_u union buffer: k_fill writes per-node buckets of H-ROW BYTE OFFSETS
// (src << 8); k_agg consumes node i's bucket fully before overwriting the same
// 512B region with node i's fp32 agg row; k_final reads float.
// g_h holds PRE-SCALED rows: h_scaled[s] = isd[s] * (x@W)[s]  (fp16)
__device__ __align__(16) __half g_h [(size_t)NN * FH];   // 25.6 MB
__device__ __align__(16) int    g_u [(size_t)NN * CAP];  // 51.2 MB  buckets -> agg
__device__ int   g_cursor[NN];                // per-node fill cursor == in-degree
__device__ float g_sum[FH];
__device__ float g_sumsq[FH];
__device__ __align__(16) float g_A[FH * 2];   // folded BN*Wlin
__device__ float g_base[2];                   // folded bias
// W in tf32 mma-B-fragment layout: [(ks*16+nt)*32 + lane] -> (b0,b1)
__device__ __align__(16) float2 g_Wf[KSTEPS * 16 * 32];

__device__ __forceinline__ unsigned f2tf32(float f) {
    unsigned u;
    asm("cvt.rna.tf32.f32 %0, %1;" : "=r"(u) : "f"(f));
    return u;
}

// ---------------- K0: zero per-replay state + build W fragments ----------------
__global__ void k_init(const float* __restrict__ W) {
    int i = blockIdx.x * blockDim.x + threadIdx.x;
    if (i < NN) g_cursor[i] = 0;
    if (i < FH) { g_sum[i] = 0.f; g_sumsq[i] = 0.f; }
    if (i < KSTEPS * 16 * 32) {
        int lane = i & 31, nt = (i >> 5) & 15, ks = i >> 9;
        int kk = ks * 8 + (lane & 3);
        int n  = nt * 8 + (lane >> 2);
        float b0 = (kk     < FIN) ? W[(size_t)kk * 128 + n]       : 0.f;
        float b1 = (kk + 4 < FIN) ? W[(size_t)(kk + 4) * 128 + n] : 0.f;
        float2 v;
        v.x = __uint_as_float(f2tf32(b0));
        v.y = __uint_as_float(f2tf32(b1));
        g_Wf[i] = v;
    }
}

// ---------------- K1: bucketed fill; stores (src << 8) = g_h row byte offset ----
__global__ void k_fill(const int* __restrict__ src, const int* __restrict__ dst) {
    int e4 = blockIdx.x * blockDim.x + threadIdx.x;
    if (e4 * 4 + 3 < NE) {
        int4 d = *reinterpret_cast<const int4*>(&dst[e4 * 4]);
        int4 s = *reinterpret_cast<const int4*>(&src[e4 * 4]);
        int p;
        p = atomicAdd(&g_cursor[d.x], 1); if (p < CAP) g_u[(size_t)d.x * CAP + p] = s.x << 8;
        p = atomicAdd(&g_cursor[d.y], 1); if (p < CAP) g_u[(size_t)d.y * CAP + p] = s.y << 8;
        p = atomicAdd(&g_cursor[d.z], 1); if (p < CAP) g_u[(size_t)d.z * CAP + p] = s.z << 8;
        p = atomicAdd(&g_cursor[d.w], 1); if (p < CAP) g_u[(size_t)d.w * CAP + p] = s.w << 8;
    } else {
        for (int e = e4 * 4; e < NE; e++) {
            int d = dst[e];
            int p = atomicAdd(&g_cursor[d], 1);
            if (p < CAP) g_u[(size_t)d * CAP + p] = src[e] << 8;
        }
    }
}

// ---------------- K2: h_scaled = isd .* (x @ W)  via tf32 tensor cores -----------
__global__ void __launch_bounds__(128) k_gemm(const float* __restrict__ x) {
    __shared__ unsigned sX[64 * 108];   // row stride 108 -> conflict-free A frags
    int t    = threadIdx.x;
    int warp = t >> 5, lane = t & 31;
    int row0 = blockIdx.x * 64;

    for (int idx = t; idx < 64 * 26; idx += 128) {
        int r = idx / 26, c4 = idx - r * 26;
        float4 v = make_float4(0.f, 0.f, 0.f, 0.f);
        int gr = row0 + r;
        if (gr < NN && c4 < 25)
            v = *reinterpret_cast<const float4*>(&x[(size_t)gr * FIN + c4 * 4]);
        uint4 u;
        u.x = f2tf32(v.x); u.y = f2tf32(v.y);
        u.z = f2tf32(v.z); u.w = f2tf32(v.w);
        *reinterpret_cast<uint4*>(&sX[r * 108 + c4 * 4]) = u;
    }
    __syncthreads();

    float acc[16][4];
#pragma unroll
    for (int nt = 0; nt < 16; nt++)
#pragma unroll
        for (int c = 0; c < 4; c++) acc[nt][c] = 0.f;

    int ar = warp * 16 + (lane >> 2);
#pragma unroll
    for (int ks = 0; ks < KSTEPS; ks++) {
        int c0 = ks * 8 + (lane & 3);
        unsigned a0 = sX[ar * 108 + c0];
        unsigned a1 = sX[(ar + 8) * 108 + c0];
        unsigned a2 = sX[ar * 108 + c0 + 4];
        unsigned a3 = sX[(ar + 8) * 108 + c0 + 4];
#pragma unroll
        for (int nt = 0; nt < 16; nt++) {
            float2 b = g_Wf[(ks * 16 + nt) * 32 + lane];
            unsigned b0 = __float_as_uint(b.x);
            unsigned b1 = __float_as_uint(b.y);
            asm("mma.sync.aligned.m16n8k8.row.col.f32.tf32.tf32.f32 "
                "{%0,%1,%2,%3}, {%4,%5,%6,%7}, {%8,%9}, {%0,%1,%2,%3};"
                : "+f"(acc[nt][0]), "+f"(acc[nt][1]),
                  "+f"(acc[nt][2]), "+f"(acc[nt][3])
                : "r"(a0), "r"(a1), "r"(a2), "r"(a3), "r"(b0), "r"(b1));
        }
    }

    int gr0 = row0 + warp * 16 + (lane >> 2);
    float is0 = (gr0     < NN) ? rsqrtf((float)(g_cursor[gr0]     + 1)) : 0.f;
    float is1 = (gr0 + 8 < NN) ? rsqrtf((float)(g_cursor[gr0 + 8] + 1)) : 0.f;
#pragma unroll
    for (int nt = 0; nt < 16; nt++) {
        int col = nt * 8 + 2 * (lane & 3);
        __half2 lo = __floats2half2_rn(acc[nt][0] * is0, acc[nt][1] * is0);
        __half2 hi = __floats2half2_rn(acc[nt][2] * is1, acc[nt][3] * is1);
        if (gr0 < NN)
            *reinterpret_cast<unsigned*>(&g_h[(size_t)gr0 * FH + col]) =
                *reinterpret_cast<unsigned*>(&lo);
        if (gr0 + 8 < NN)
            *reinterpret_cast<unsigned*>(&g_h[(size_t)(gr0 + 8) * FH + col]) =
                *reinterpret_cast<unsigned*>(&hi);
    }
}

// ---------------- K3: warp-per-node gather aggregation + fused BN stats ----------
// Per edge: SHFL(offset) + IADD + LDG.64 + 2xHADD2; fp16 partials flushed to
// fp32 every 8 edges. agg_i = isd_i * (sum h_scaled[s] + h_scaled[i]) + b
__global__ void __launch_bounds__(256) k_agg(const float* __restrict__ b) {
    __shared__ float s1[8][FH];
    __shared__ float s2[8][FH];
    int t = threadIdx.x, w = t >> 5, l = t & 31;

    float4 bv = *reinterpret_cast<const float4*>(&b[4 * l]);
    const char* hbase = reinterpret_cast<const char*>(g_h) + 8 * l;

    float sx0 = 0.f, sx1 = 0.f, sx2 = 0.f, sx3 = 0.f;
    float sq0 = 0.f, sq1 = 0.f, sq2 = 0.f, sq3 = 0.f;

    int gw = blockIdx.x * 8 + w;
    int nw = gridDim.x * 8;
    for (int i = gw; i < NN; i += nw) {
        size_t beg = (size_t)i * CAP;
        int cur = g_cursor[i];
        int deg = min(cur, CAP);
        float isd_i = rsqrtf((float)(cur + 1));
        float a0 = 0.f, a1 = 0.f, a2 = 0.f, a3 = 0.f;
        for (int base = 0; base < deg; base += 32) {
            int idx = base + l;
            int off = 0;
            if (idx < deg) off = g_u[beg + idx];
            int cnt = min(32, deg - base);
            int sub = 0;
            for (; sub + 8 <= cnt; sub += 8) {
                __half2 c01 = __half2half2(__ushort_as_half(0));
                __half2 c23 = c01;
#pragma unroll
                for (int j = 0; j < 8; j++) {
                    int o = __shfl_sync(0xffffffffu, off, sub + j);
                    uint2 u = *reinterpret_cast<const uint2*>(hbase + o);
                    c01 = __hadd2(c01, *reinterpret_cast<__half2*>(&u.x));
                    c23 = __hadd2(c23, *reinterpret_cast<__half2*>(&u.y));
                }
                float2 f01 = __half22float2(c01);
                float2 f23 = __half22float2(c23);
                a0 += f01.x; a1 += f01.y;
                a2 += f23.x; a3 += f23.y;
            }
            for (; sub < cnt; sub++) {
                int o = __shfl_sync(0xffffffffu, off, sub);
                uint2 u = *reinterpret_cast<const uint2*>(hbase + o);
                float2 f01 = __half22float2(*reinterpret_cast<__half2*>(&u.x));
                float2 f23 = __half22float2(*reinterpret_cast<__half2*>(&u.y));
                a0 += f01.x; a1 += f01.y;
                a2 += f23.x; a3 += f23.y;
            }
        }
        { // self loop: add own prescaled row (fp32 path)
            uint2 u = *reinterpret_cast<const uint2*>(hbase + ((size_t)i << 8));
            float2 f01 = __half22float2(*reinterpret_cast<__half2*>(&u.x));
            float2 f23 = __half22float2(*reinterpret_cast<__half2*>(&u.y));
            a0 += f01.x; a1 += f01.y;
            a2 += f23.x; a3 += f23.y;
        }
        a0 = a0 * isd_i + bv.x;
        a1 = a1 * isd_i + bv.y;
        a2 = a2 * isd_i + bv.z;
        a3 = a3 * isd_i + bv.w;
        *reinterpret_cast<float4*>(
            reinterpret_cast<float*>(g_u) + (size_t)i * FH + 4 * l) =
            make_float4(a0, a1, a2, a3);
        sx0 += a0; sx1 += a1; sx2 += a2; sx3 += a3;
        sq0 += a0 * a0; sq1 += a1 * a1; sq2 += a2 * a2; sq3 += a3 * a3;
    }
    s1[w][4 * l + 0] = sx0; s1[w][4 * l + 1] = sx1;
    s1[w][4 * l + 2] = sx2; s1[w][4 * l + 3] = sx3;
    s2[w][4 * l + 0] = sq0; s2[w][4 * l + 1] = sq1;
    s2[w][4 * l + 2] = sq2; s2[w][4 * l + 3] = sq3;
    __syncthreads();
    if (t < FH) {
        float v = 0.f;
#pragma unroll
        for (int ww = 0; ww < 8; ww++) v += s1[ww][t];
        atomicAdd(&g_sum[t], v);
    } else {
        int c = t - FH;
        float v = 0.f;
#pragma unroll
        for (int ww = 0; ww < 8; ww++) v += s2[ww][c];
        atomicAdd(&g_sumsq[c], v);
    }
}

// ---------------- K4: fold BN into linear layer ----------------
__global__ void k_stats(const float* __restrict__ gamma, const float* __restrict__ beta,
                        const float* __restrict__ Wl,    const float* __restrict__ blin) {
    __shared__ float r0[128], r1[128];
    int c = threadIdx.x;
    float mean   = g_sum[c]   * (1.f / (float)NN);
    float var    = g_sumsq[c] * (1.f / (float)NN) - mean * mean;
    float invstd = rsqrtf(var + BNEPS);
    float scale  = invstd * gamma[c];
    float shift  = beta[c] - mean * scale;
    float w0 = Wl[c * 2 + 0], w1 = Wl[c * 2 + 1];
    g_A[c * 2 + 0] = scale * w0;
    g_A[c * 2 + 1] = scale * w1;
    r0[c] = shift * w0;
    r1[c] = shift * w1;
    __syncthreads();
    for (int o = 64; o; o >>= 1) {
        if (c < o) { r0[c] += r0[c + o]; r1[c] += r1[c + o]; }
        __syncthreads();
    }
    if (c == 0) {
        g_base[0] = blin[0] + r0[0];
        g_base[1] = blin[1] + r1[0];
    }
}

// ---------------- K5: linear + relu + softmax + mask ----------------
__global__ void __launch_bounds__(256) k_final(const int* __restrict__ mask,
                                               float* __restrict__ out) {
    int t = threadIdx.x, w = t >> 5, l = t & 31;
    int i = blockIdx.x * 8 + w;
    if (i >= NN) return;
    const float* agg = reinterpret_cast<const float*>(g_u);
    const float4 v  = *reinterpret_cast<const float4*>(&agg[(size_t)i * FH + 4 * l]);
    const float4 A0 = *reinterpret_cast<const float4*>(&g_A[8 * l]);
    const float4 A1 = *reinterpret_cast<const float4*>(&g_A[8 * l + 4]);
    float p0 = v.x * A0.x + v.y * A0.z + v.z * A1.x + v.w * A1.z;
    float p1 = v.x * A0.y + v.y * A0.w + v.z * A1.y + v.w * A1.w;
#pragma unroll
    for (int o = 16; o; o >>= 1) {
        p0 += __shfl_xor_sync(0xffffffffu, p0, o);
        p1 += __shfl_xor_sync(0xffffffffu, p1, o);
    }
    if (l == 0) {
        float l0 = fmaxf(p0 + g_base[0], 0.f);
        float l1 = fmaxf(p1 + g_base[1], 0.f);
        float m  = fmaxf(l0, l1);
        float e0 = expf(l0 - m);
        float e1 = expf(l1 - m);
        float inv = 1.f / (e0 + e1);
        float mk = (mask[i] != 0) ? 1.f : 0.f;
        *reinterpret_cast<float2*>(&out[(size_t)i * 2]) =
            make_float2(e0 * inv * mk, e1 * inv * mk);
    }
}

// ---------------- launch ----------------
extern "C" void kernel_launch(void* const* d_in, const int* in_sizes, int n_in,
                              void* d_out, int out_size) {
    const float* state = (const float*)d_in[0];
    const float* W     = (const float*)d_in[1];
    const float* b     = (const float*)d_in[2];
    const float* gamma = (const float*)d_in[3];
    const float* beta  = (const float*)d_in[4];
    const float* Wlin  = (const float*)d_in[5];
    const float* blin  = (const float*)d_in[6];
    const int*   ei    = (const int*)d_in[7];
    const int*   mask  = (const int*)d_in[8];
    float* out = (float*)d_out;

    const int* src = ei;        // edge_index[0]
    const int* dst = ei + NE;   // edge_index[1]

    k_init <<<(NN + 255) / 256, 256>>>(W);                 // 1
    k_fill <<<((NE / 4) + 255) / 256, 256>>>(src, dst);    // 2
    k_gemm <<<(NN + 63) / 64, 128>>>(state);               // 3 (needs g_cursor)
    k_agg  <<<2368, 256>>>(b);                             // 4  <- profiled slot
    k_stats<<<1, 128>>>(gamma, beta, Wlin, blin);          // 5
    k_final<<<NN / 8, 256>>>(mask, out);                   // 6
}

// round 17
// speedup vs baseline: 1.0765x; 1.0765x over previous
#include <cuda_runtime.h>
#include <cuda_fp16.h>
#include <cstdint>

#define NN   100000
#define NE   3200000
#define FH   128
#define FIN  100
#define BNEPS 1e-5f
#define CAP  128       // bucket slots/node == agg row size; Poisson(32) tail ~e^-90
#define KSTEPS 13      // K=100 padded to 104 = 13 x 8

// ---------------- scratch (static device globals; no allocation) ----------------
// g_u union buffer: k_fill writes per-node buckets of H-ROW BYTE OFFSETS
// (src << 8); k_agg consumes node i's bucket fully before overwriting the same
// 512B region with node i's fp32 agg row; k_final reads float.
// g_h holds PRE-SCALED rows: h_scaled[s] = isd[s] * (x@W)[s]  (fp16)
__device__ __align__(16) __half g_h [(size_t)NN * FH];   // 25.6 MB
__device__ __align__(16) int    g_u [(size_t)NN * CAP];  // 51.2 MB  buckets -> agg
__device__ int   g_cursor[NN];                // per-node fill cursor == in-degree
__device__ float g_sum[FH];
__device__ float g_sumsq[FH];
__device__ __align__(16) float g_A[FH * 2];   // folded BN*Wlin
__device__ float g_base[2];                   // folded bias
// W in tf32 mma-B-fragment layout: [(ks*16+nt)*32 + lane] -> (b0,b1)
__device__ __align__(16) float2 g_Wf[KSTEPS * 16 * 32];

__device__ __forceinline__ unsigned f2tf32(float f) {
    unsigned u;
    asm("cvt.rna.tf32.f32 %0, %1;" : "=r"(u) : "f"(f));
    return u;
}

// ---------------- K0: zero per-replay state + build W fragments ----------------
__global__ void k_init(const float* __restrict__ W) {
    int i = blockIdx.x * blockDim.x + threadIdx.x;
    if (i < NN) g_cursor[i] = 0;
    if (i < FH) { g_sum[i] = 0.f; g_sumsq[i] = 0.f; }
    if (i < KSTEPS * 16 * 32) {
        int lane = i & 31, nt = (i >> 5) & 15, ks = i >> 9;
        int kk = ks * 8 + (lane & 3);
        int n  = nt * 8 + (lane >> 2);
        float b0 = (kk     < FIN) ? W[(size_t)kk * 128 + n]       : 0.f;
        float b1 = (kk + 4 < FIN) ? W[(size_t)(kk + 4) * 128 + n] : 0.f;
        float2 v;
        v.x = __uint_as_float(f2tf32(b0));
        v.y = __uint_as_float(f2tf32(b1));
        g_Wf[i] = v;
    }
}

// ---------------- K1: bucketed fill; stores (src << 8) = g_h row byte offset ----
__global__ void k_fill(const int* __restrict__ src, const int* __restrict__ dst) {
    int e4 = blockIdx.x * blockDim.x + threadIdx.x;
    if (e4 * 4 + 3 < NE) {
        int4 d = *reinterpret_cast<const int4*>(&dst[e4 * 4]);
        int4 s = *reinterpret_cast<const int4*>(&src[e4 * 4]);
        int p;
        p = atomicAdd(&g_cursor[d.x], 1); if (p < CAP) g_u[(size_t)d.x * CAP + p] = s.x << 8;
        p = atomicAdd(&g_cursor[d.y], 1); if (p < CAP) g_u[(size_t)d.y * CAP + p] = s.y << 8;
        p = atomicAdd(&g_cursor[d.z], 1); if (p < CAP) g_u[(size_t)d.z * CAP + p] = s.z << 8;
        p = atomicAdd(&g_cursor[d.w], 1); if (p < CAP) g_u[(size_t)d.w * CAP + p] = s.w << 8;
    } else {
        for (int e = e4 * 4; e < NE; e++) {
            int d = dst[e];
            int p = atomicAdd(&g_cursor[d], 1);
            if (p < CAP) g_u[(size_t)d * CAP + p] = src[e] << 8;
        }
    }
}

// ---------------- K2: h_scaled = isd .* (x @ W)  via tf32 tensor cores -----------
__global__ void __launch_bounds__(128) k_gemm(const float* __restrict__ x) {
    __shared__ unsigned sX[64 * 108];   // row stride 108 -> conflict-free A frags
    int t    = threadIdx.x;
    int warp = t >> 5, lane = t & 31;
    int row0 = blockIdx.x * 64;

    for (int idx = t; idx < 64 * 26; idx += 128) {
        int r = idx / 26, c4 = idx - r * 26;
        float4 v = make_float4(0.f, 0.f, 0.f, 0.f);
        int gr = row0 + r;
        if (gr < NN && c4 < 25)
            v = *reinterpret_cast<const float4*>(&x[(size_t)gr * FIN + c4 * 4]);
        uint4 u;
        u.x = f2tf32(v.x); u.y = f2tf32(v.y);
        u.z = f2tf32(v.z); u.w = f2tf32(v.w);
        *reinterpret_cast<uint4*>(&sX[r * 108 + c4 * 4]) = u;
    }
    __syncthreads();

    float acc[16][4];
#pragma unroll
    for (int nt = 0; nt < 16; nt++)
#pragma unroll
        for (int c = 0; c < 4; c++) acc[nt][c] = 0.f;

    int ar = warp * 16 + (lane >> 2);
#pragma unroll
    for (int ks = 0; ks < KSTEPS; ks++) {
        int c0 = ks * 8 + (lane & 3);
        unsigned a0 = sX[ar * 108 + c0];
        unsigned a1 = sX[(ar + 8) * 108 + c0];
        unsigned a2 = sX[ar * 108 + c0 + 4];
        unsigned a3 = sX[(ar + 8) * 108 + c0 + 4];
#pragma unroll
        for (int nt = 0; nt < 16; nt++) {
            float2 b = g_Wf[(ks * 16 + nt) * 32 + lane];
            unsigned b0 = __float_as_uint(b.x);
            unsigned b1 = __float_as_uint(b.y);
            asm("mma.sync.aligned.m16n8k8.row.col.f32.tf32.tf32.f32 "
                "{%0,%1,%2,%3}, {%4,%5,%6,%7}, {%8,%9}, {%0,%1,%2,%3};"
                : "+f"(acc[nt][0]), "+f"(acc[nt][1]),
                  "+f"(acc[nt][2]), "+f"(acc[nt][3])
                : "r"(a0), "r"(a1), "r"(a2), "r"(a3), "r"(b0), "r"(b1));
        }
    }

    int gr0 = row0 + warp * 16 + (lane >> 2);
    float is0 = (gr0     < NN) ? rsqrtf((float)(g_cursor[gr0]     + 1)) : 0.f;
    float is1 = (gr0 + 8 < NN) ? rsqrtf((float)(g_cursor[gr0 + 8] + 1)) : 0.f;
#pragma unroll
    for (int nt = 0; nt < 16; nt++) {
        int col = nt * 8 + 2 * (lane & 3);
        __half2 lo = __floats2half2_rn(acc[nt][0] * is0, acc[nt][1] * is0);
        __half2 hi = __floats2half2_rn(acc[nt][2] * is1, acc[nt][3] * is1);
        if (gr0 < NN)
            *reinterpret_cast<unsigned*>(&g_h[(size_t)gr0 * FH + col]) =
                *reinterpret_cast<unsigned*>(&lo);
        if (gr0 + 8 < NN)
            *reinterpret_cast<unsigned*>(&g_h[(size_t)(gr0 + 8) * FH + col]) =
                *reinterpret_cast<unsigned*>(&hi);
    }
}

// ---------------- K3: warp-per-node gather aggregation + fused BN stats ----------
// 16-edge subchunks (MLP=16, dual fp16 accumulator chains), 4-edge mid-tier,
// scalar tail. agg_i = isd_i * (sum h_scaled[s] + h_scaled[i]) + b
__global__ void __launch_bounds__(256) k_agg(const float* __restrict__ b) {
    __shared__ float s1[8][FH];
    __shared__ float s2[8][FH];
    int t = threadIdx.x, w = t >> 5, l = t & 31;

    float4 bv = *reinterpret_cast<const float4*>(&b[4 * l]);
    const char* hbase = reinterpret_cast<const char*>(g_h) + 8 * l;
    const __half2 hz = __half2half2(__ushort_as_half(0));

    float sx0 = 0.f, sx1 = 0.f, sx2 = 0.f, sx3 = 0.f;
    float sq0 = 0.f, sq1 = 0.f, sq2 = 0.f, sq3 = 0.f;

    int gw = blockIdx.x * 8 + w;
    int nw = gridDim.x * 8;
    for (int i = gw; i < NN; i += nw) {
        size_t beg = (size_t)i * CAP;
        int cur = g_cursor[i];
        int deg = min(cur, CAP);
        float isd_i = rsqrtf((float)(cur + 1));
        float a0 = 0.f, a1 = 0.f, a2 = 0.f, a3 = 0.f;
        for (int base = 0; base < deg; base += 32) {
            int idx = base + l;
            int off = 0;
            if (idx < deg) off = g_u[beg + idx];
            int cnt = min(32, deg - base);
            int j = 0;
            // 16-edge subchunks: 16 batched LDGs, two independent HADD2 chains
            for (; j + 16 <= cnt; j += 16) {
                __half2 cA0 = hz, cA1 = hz, cB0 = hz, cB1 = hz;
#pragma unroll
                for (int q = 0; q < 8; q++) {
                    int o0 = __shfl_sync(0xffffffffu, off, j + 2 * q);
                    int o1 = __shfl_sync(0xffffffffu, off, j + 2 * q + 1);
                    uint2 ua = *reinterpret_cast<const uint2*>(hbase + o0);
                    uint2 ub = *reinterpret_cast<const uint2*>(hbase + o1);
                    cA0 = __hadd2(cA0, *reinterpret_cast<__half2*>(&ua.x));
                    cA1 = __hadd2(cA1, *reinterpret_cast<__half2*>(&ua.y));
                    cB0 = __hadd2(cB0, *reinterpret_cast<__half2*>(&ub.x));
                    cB1 = __hadd2(cB1, *reinterpret_cast<__half2*>(&ub.y));
                }
                float2 fa0 = __half22float2(cA0), fa1 = __half22float2(cA1);
                float2 fb0 = __half22float2(cB0), fb1 = __half22float2(cB1);
                a0 += fa0.x + fb0.x; a1 += fa0.y + fb0.y;
                a2 += fa1.x + fb1.x; a3 += fa1.y + fb1.y;
            }
            // 4-edge subchunks
            for (; j + 4 <= cnt; j += 4) {
                __half2 c0 = hz, c1 = hz;
#pragma unroll
                for (int q = 0; q < 4; q++) {
                    int o = __shfl_sync(0xffffffffu, off, j + q);
                    uint2 u = *reinterpret_cast<const uint2*>(hbase + o);
                    c0 = __hadd2(c0, *reinterpret_cast<__half2*>(&u.x));
                    c1 = __hadd2(c1, *reinterpret_cast<__half2*>(&u.y));
                }
                float2 f0 = __half22float2(c0), f1 = __half22float2(c1);
                a0 += f0.x; a1 += f0.y;
                a2 += f1.x; a3 += f1.y;
            }
            // scalar tail (<=3 edges)
            for (; j < cnt; j++) {
                int o = __shfl_sync(0xffffffffu, off, j);
                uint2 u = *reinterpret_cast<const uint2*>(hbase + o);
                float2 f01 = __half22float2(*reinterpret_cast<__half2*>(&u.x));
                float2 f23 = __half22float2(*reinterpret_cast<__half2*>(&u.y));
                a0 += f01.x; a1 += f01.y;
                a2 += f23.x; a3 += f23.y;
            }
        }
        { // self loop: add own prescaled row (fp32 path)
            uint2 u = *reinterpret_cast<const uint2*>(hbase + ((size_t)i << 8));
            float2 f01 = __half22float2(*reinterpret_cast<__half2*>(&u.x));
            float2 f23 = __half22float2(*reinterpret_cast<__half2*>(&u.y));
            a0 += f01.x; a1 += f01.y;
            a2 += f23.x; a3 += f23.y;
        }
        a0 = a0 * isd_i + bv.x;
        a1 = a1 * isd_i + bv.y;
        a2 = a2 * isd_i + bv.z;
        a3 = a3 * isd_i + bv.w;
        *reinterpret_cast<float4*>(
            reinterpret_cast<float*>(g_u) + (size_t)i * FH + 4 * l) =
            make_float4(a0, a1, a2, a3);
        sx0 += a0; sx1 += a1; sx2 += a2; sx3 += a3;
        sq0 += a0 * a0; sq1 += a1 * a1; sq2 += a2 * a2; sq3 += a3 * a3;
    }
    s1[w][4 * l + 0] = sx0; s1[w][4 * l + 1] = sx1;
    s1[w][4 * l + 2] = sx2; s1[w][4 * l + 3] = sx3;
    s2[w][4 * l + 0] = sq0; s2[w][4 * l + 1] = sq1;
    s2[w][4 * l + 2] = sq2; s2[w][4 * l + 3] = sq3;
    __syncthreads();
    if (t < FH) {
        float v = 0.f;
#pragma unroll
        for (int ww = 0; ww < 8; ww++) v += s1[ww][t];
        atomicAdd(&g_sum[t], v);
    } else {
        int c = t - FH;
        float v = 0.f;
#pragma unroll
        for (int ww = 0; ww < 8; ww++) v += s2[ww][c];
        atomicAdd(&g_sumsq[c], v);
    }
}

// ---------------- K4: fold BN into linear layer ----------------
__global__ void k_stats(const float* __restrict__ gamma, const float* __restrict__ beta,
                        const float* __restrict__ Wl,    const float* __restrict__ blin) {
    __shared__ float r0[128], r1[128];
    int c = threadIdx.x;
    float mean   = g_sum[c]   * (1.f / (float)NN);
    float var    = g_sumsq[c] * (1.f / (float)NN) - mean * mean;
    float invstd = rsqrtf(var + BNEPS);
    float scale  = invstd * gamma[c];
    float shift  = beta[c] - mean * scale;
    float w0 = Wl[c * 2 + 0], w1 = Wl[c * 2 + 1];
    g_A[c * 2 + 0] = scale * w0;
    g_A[c * 2 + 1] = scale * w1;
    r0[c] = shift * w0;
    r1[c] = shift * w1;
    __syncthreads();
    for (int o = 64; o; o >>= 1) {
        if (c < o) { r0[c] += r0[c + o]; r1[c] += r1[c + o]; }
        __syncthreads();
    }
    if (c == 0) {
        g_base[0] = blin[0] + r0[0];
        g_base[1] = blin[1] + r1[0];
    }
}

// ---------------- K5: linear + relu + softmax + mask ----------------
__global__ void __launch_bounds__(256) k_final(const int* __restrict__ mask,
                                               float* __restrict__ out) {
    int t = threadIdx.x, w = t >> 5, l = t & 31;
    int i = blockIdx.x * 8 + w;
    if (i >= NN) return;
    const float* agg = reinterpret_cast<const float*>(g_u);
    const float4 v  = *reinterpret_cast<const float4*>(&agg[(size_t)i * FH + 4 * l]);
    const float4 A0 = *reinterpret_cast<const float4*>(&g_A[8 * l]);
    const float4 A1 = *reinterpret_cast<const float4*>(&g_A[8 * l + 4]);
    float p0 = v.x * A0.x + v.y * A0.z + v.z * A1.x + v.w * A1.z;
    float p1 = v.x * A0.y + v.y * A0.w + v.z * A1.y + v.w * A1.w;
#pragma unroll
    for (int o = 16; o; o >>= 1) {
        p0 += __shfl_xor_sync(0xffffffffu, p0, o);
        p1 += __shfl_xor_sync(0xffffffffu, p1, o);
    }
    if (l == 0) {
        float l0 = fmaxf(p0 + g_base[0], 0.f);
        float l1 = fmaxf(p1 + g_base[1], 0.f);
        float m  = fmaxf(l0, l1);
        float e0 = expf(l0 - m);
        float e1 = expf(l1 - m);
        float inv = 1.f / (e0 + e1);
        float mk = (mask[i] != 0) ? 1.f : 0.f;
        *reinterpret_cast<float2*>(&out[(size_t)i * 2]) =
            make_float2(e0 * inv * mk, e1 * inv * mk);
    }
}

// ---------------- launch ----------------
extern "C" void kernel_launch(void* const* d_in, const int* in_sizes, int n_in,
                              void* d_out, int out_size) {
    const float* state = (const float*)d_in[0];
    const float* W     = (const float*)d_in[1];
    const float* b     = (const float*)d_in[2];
    const float* gamma = (const float*)d_in[3];
    const float* beta  = (const float*)d_in[4];
    const float* Wlin  = (const float*)d_in[5];
    const float* blin  = (const float*)d_in[6];
    const int*   ei    = (const int*)d_in[7];
    const int*   mask  = (const int*)d_in[8];
    float* out = (float*)d_out;

    const int* src = ei;        // edge_index[0]
    const int* dst = ei + NE;   // edge_index[1]

    k_init <<<(NN + 255) / 256, 256>>>(W);                 // 1
    k_fill <<<((NE / 4) + 255) / 256, 256>>>(src, dst);    // 2
    k_gemm <<<(NN + 63) / 64, 128>>>(state);               // 3 (needs g_cursor)
    k_agg  <<<2368, 256>>>(b);                             // 4  <- profiled slot
    k_stats<<<1, 128>>>(gamma, beta, Wlin, blin);          // 5
    k_final<<<NN / 8, 256>>>(mask, out);                   // 6
}